// round 15
// baseline (speedup 1.0000x reference)
#include <cuda_runtime.h>
#include <cuda_fp16.h>
#include <cstdint>

// Problem constants
#define BATCH  16384
#define IN_DIM 1024
#define H1     2048
#define H2     2048
#define HIDD   1024
#define SPECH  2048
#define NE     8

// ---------------- scratch (static device globals; no allocation) -------------
__device__ __half g_xh[(size_t)BATCH * IN_DIM];
__device__ __half g_z1[(size_t)BATCH * H1];
__device__ __half g_z2[(size_t)BATCH * H2];
__device__ __half g_z [(size_t)BATCH * HIDD];
__device__ __half g_W0[(size_t)IN_DIM * H1];
__device__ __half g_W1[(size_t)H1 * H2];
__device__ __half g_W2[(size_t)H2 * HIDD];
__device__ __half g_sW1[(size_t)NE * HIDD * SPECH];
__device__ int g_perm[BATCH];
__device__ int g_off[NE + 1];
__device__ int g_cur[NE];
__device__ int g_is64;

// ---------------- helpers ----------------------------------------------------
__device__ __forceinline__ uint32_t smem_u32(const void* p) {
    return (uint32_t)__cvta_generic_to_shared(p);
}
__device__ __forceinline__ void ldsm4(uint32_t& r0, uint32_t& r1, uint32_t& r2, uint32_t& r3, uint32_t a) {
    asm volatile("ldmatrix.sync.aligned.m8n8.x4.shared.b16 {%0,%1,%2,%3},[%4];\n"
                 : "=r"(r0), "=r"(r1), "=r"(r2), "=r"(r3) : "r"(a));
}
__device__ __forceinline__ void ldsm4t(uint32_t& r0, uint32_t& r1, uint32_t& r2, uint32_t& r3, uint32_t a) {
    asm volatile("ldmatrix.sync.aligned.m8n8.x4.trans.shared.b16 {%0,%1,%2,%3},[%4];\n"
                 : "=r"(r0), "=r"(r1), "=r"(r2), "=r"(r3) : "r"(a));
}
__device__ __forceinline__ void mma16816(float* c,
                                         uint32_t a0, uint32_t a1, uint32_t a2, uint32_t a3,
                                         uint32_t b0, uint32_t b1) {
    asm volatile(
        "mma.sync.aligned.m16n8k16.row.col.f32.f16.f16.f32 "
        "{%0,%1,%2,%3},{%4,%5,%6,%7},{%8,%9},{%0,%1,%2,%3};\n"
        : "+f"(c[0]), "+f"(c[1]), "+f"(c[2]), "+f"(c[3])
        : "r"(a0), "r"(a1), "r"(a2), "r"(a3), "r"(b0), "r"(b1));
}
__device__ __forceinline__ void cp16(uint32_t dst, const void* src, uint32_t sz) {
    asm volatile("cp.async.cg.shared.global [%0], [%1], 16, %2;\n"
                 :: "r"(dst), "l"(src), "r"(sz));
}
__device__ __forceinline__ void cp_commit() {
    asm volatile("cp.async.commit_group;\n" ::: "memory");
}
__device__ __forceinline__ void cp_wait_1() {
    asm volatile("cp.async.wait_group 1;\n" ::: "memory");
}
__device__ __forceinline__ int read_d(const void* d, int i) {
    if (g_is64) return (int)((const long long*)d)[i];
    return ((const int*)d)[i];
}

// ---------------- fused fp32 -> fp16 conversion (5 segments, 1 launch) --------
// Unit = 8 elements (2x float4 in, 1x uint4 out). Grid-stride.
struct CvtArgs {
    const float* s[5];
    __half* d[5];
    int beg[6];   // cumulative 8-elem unit offsets
};
__global__ void cvt_all(CvtArgs a) {
    int stride = gridDim.x * blockDim.x;
    for (int i = blockIdx.x * blockDim.x + threadIdx.x; i < a.beg[5]; i += stride) {
        int seg = 0;
#pragma unroll
        for (int k = 1; k < 5; k++) if (i >= a.beg[k]) seg = k;
        int li = i - a.beg[seg];
        const float* s = a.s[seg];
        float4 v0 = ((const float4*)s)[2 * li];
        float4 v1 = ((const float4*)s)[2 * li + 1];
        __half2 h0 = __floats2half2_rn(v0.x, v0.y);
        __half2 h1 = __floats2half2_rn(v0.z, v0.w);
        __half2 h2 = __floats2half2_rn(v1.x, v1.y);
        __half2 h3 = __floats2half2_rn(v1.z, v1.w);
        uint4 o;
        o.x = *reinterpret_cast<uint32_t*>(&h0);
        o.y = *reinterpret_cast<uint32_t*>(&h1);
        o.z = *reinterpret_cast<uint32_t*>(&h2);
        o.w = *reinterpret_cast<uint32_t*>(&h3);
        ((uint4*)a.d[seg])[li] = o;
    }
}

// ---------------- routing -----------------------------------------------------
__global__ void setup_kernel() {
    if (threadIdx.x < NE) g_cur[threadIdx.x] = 0;
    if (threadIdx.x == 0) g_is64 = 1;
}
__global__ void detect_kernel(const int* __restrict__ w, int npairs) {
    int i = blockIdx.x * blockDim.x + threadIdx.x;
    if (i < npairs && w[2 * i + 1] != 0) g_is64 = 0;
}
__global__ void count_kernel(const void* __restrict__ d) {
    int i = blockIdx.x * blockDim.x + threadIdx.x;
    if (i < BATCH) atomicAdd(&g_cur[read_d(d, i)], 1);
}
__global__ void prefix_kernel() {
    int s = 0;
    for (int e = 0; e < NE; e++) { g_off[e] = s; s += g_cur[e]; }
    g_off[NE] = s;
    for (int e = 0; e < NE; e++) g_cur[e] = g_off[e];
}
// scatter + zero the output buffer (fused; same index space)
__global__ void scatter_kernel(const void* __restrict__ d, float* __restrict__ out) {
    int i = blockIdx.x * blockDim.x + threadIdx.x;
    if (i < BATCH) {
        int e = read_d(d, i);
        int p = atomicAdd(&g_cur[e], 1);
        g_perm[p] = i;
        out[i] = 0.f;
    }
}

// ---------------- fp16 tensor-core GEMM (3-stage cp.async, BK=64) -------------
// C[M,N] = act(A[M,K] @ B[K,N] + bias), A row-major (ldA=K), B row-major [K,N].
// SPEC: flattened grid.x encodes (expert, m-block) via g_off walk; A rows
//   gathered via g_perm; epilogue fuses the OUT=1 head:
//   atomicAdd(out[perm[row]], sum_col relu(acc+b1[col])*w2[col])
//   (+ b2[e] exactly once: blockIdx.y==0 && wn==0).
#define BM 128
#define BN 128
#define BK 64
#define LDA 72
#define LDB 136
#define STAGES 3
#define ABUF_B (BM * LDA * 2)   // 18432 bytes per A stage
#define BBUF_B (BK * LDB * 2)   // 17408 bytes per B stage
#define SMEM_BYTES (STAGES * (ABUF_B + BBUF_B))   // 107520
#define SPEC_GRID_X (BATCH / BM + NE)             // 136: worst case sum of ceils

template <bool RELU, bool SPEC>
__global__ __launch_bounds__(256, 2) void gemm_kernel(
    const __half* __restrict__ A, const __half* __restrict__ Bw,
    const float* __restrict__ bias, __half* __restrict__ C,
    float* __restrict__ outp, const float* __restrict__ w2v,
    const float* __restrict__ b2v, int N, int K) {
    extern __shared__ __align__(16) char dynsm[];
    __half (*sA)[BM][LDA] = reinterpret_cast<__half (*)[BM][LDA]>(dynsm);
    __half (*sB)[BK][LDB] = reinterpret_cast<__half (*)[BK][LDB]>(dynsm + STAGES * ABUF_B);

    int m0 = blockIdx.x * BM;
    const int n0 = blockIdx.y * BN;
    int mCount = BATCH;
    int eIdx = 0;
    const int* rowmap = nullptr;
    if (SPEC) {
        // decode flattened (expert, m-block) from blockIdx.x
        int flat = blockIdx.x;
        int e = 0, mb = flat, nb;
#pragma unroll
        for (e = 0; e < NE; e++) {
            int cnt = g_off[e + 1] - g_off[e];
            nb = (cnt + BM - 1) / BM;
            if (mb < nb) break;
            mb -= nb;
        }
        if (e >= NE) return;
        eIdx = e;
        int beg = g_off[eIdx];
        mCount = g_off[eIdx + 1] - beg;
        m0 = mb * BM;
        rowmap = g_perm + beg;
        Bw   += (size_t)eIdx * K * N;
        bias += (size_t)eIdx * N;
    }

    const int tid  = threadIdx.x;
    const int lane = tid & 31;
    const int warp = tid >> 5;
    const int wm = warp >> 2;  // 0..1  (M)
    const int wn = warp & 3;   // 0..3  (N)

    float acc[4][4][4];
#pragma unroll
    for (int i = 0; i < 4; i++)
#pragma unroll
        for (int j = 0; j < 4; j++)
#pragma unroll
            for (int k = 0; k < 4; k++) acc[i][j][k] = 0.f;

    // ---- per-thread load descriptors ----
    const char* aSrc[4]; uint32_t aSz[4];
    const int aRow0 = tid >> 3, aCs = (tid & 7) << 3;  // cs in halves
#pragma unroll
    for (int li = 0; li < 4; li++) {
        int r = aRow0 + li * 32;
        int gr = m0 + r;
        bool ok = true;
        int grow = gr;
        if (SPEC) {
            ok = gr < mCount;
            grow = ok ? rowmap[gr] : 0;
        }
        aSrc[li] = (const char*)(A + (size_t)grow * K + aCs);
        aSz[li]  = ok ? 16u : 0u;
    }
    const uint32_t aOff0 = smem_u32(&sA[0][aRow0][aCs]);   // + li*32*LDA*2
    const int bRow0 = tid >> 4, bCs = (tid & 15) << 3;
    const char* bSrc0 = (const char*)(Bw + (size_t)bRow0 * N + n0 + bCs);
    const uint32_t bOff0 = smem_u32(&sB[0][bRow0][bCs]);   // + li*16*LDB*2
    const size_t bRowStep = (size_t)16 * N * 2;            // 16 rows in bytes
    const size_t bStep = (size_t)BK * N * 2;               // bytes per k-chunk
    const int nk = K >> 6;

    // prologue: prefetch chunks 0,1 into stages 0,1
#pragma unroll
    for (int s = 0; s < STAGES - 1; s++) {
        if (s < nk) {
            uint32_t ab = (uint32_t)s * ABUF_B;
            uint32_t bb = (uint32_t)s * BBUF_B;
            long ka = (long)s * 128;             // 64 halves = 128 bytes per chunk
#pragma unroll
            for (int li = 0; li < 4; li++)
                cp16(aOff0 + ab + li * (32 * LDA * 2), aSrc[li] + ka, aSz[li]);
#pragma unroll
            for (int li = 0; li < 4; li++)
                cp16(bOff0 + bb + li * (16 * LDB * 2),
                     bSrc0 + (size_t)s * bStep + li * bRowStep, 16u);
        }
        cp_commit();
    }

    int buf = 0, wbuf = STAGES - 1;
    for (int i = 0; i < nk; i++) {
        cp_wait_1();          // chunk i complete (<=1 younger group in flight)
        __syncthreads();      // all warps done with stage being overwritten below
        int nxt = i + STAGES - 1;
        if (nxt < nk) {
            uint32_t ab = (uint32_t)wbuf * ABUF_B;
            uint32_t bb = (uint32_t)wbuf * BBUF_B;
            long ka = (long)nxt * 128;
#pragma unroll
            for (int li = 0; li < 4; li++)
                cp16(aOff0 + ab + li * (32 * LDA * 2), aSrc[li] + ka, aSz[li]);
#pragma unroll
            for (int li = 0; li < 4; li++)
                cp16(bOff0 + bb + li * (16 * LDB * 2),
                     bSrc0 + (size_t)nxt * bStep + li * bRowStep, 16u);
        }
        cp_commit();          // unconditional: keeps group-count invariant at tail

#pragma unroll
        for (int kk = 0; kk < BK; kk += 16) {
            uint32_t bf[2][4];
#pragma unroll
            for (int bi = 0; bi < 2; bi++) {
                const __half* p = &sB[buf][kk + (lane & 15)][wn * 32 + bi * 16 + ((lane >> 4) << 3)];
                ldsm4t(bf[bi][0], bf[bi][1], bf[bi][2], bf[bi][3], smem_u32(p));
            }
            uint32_t af[4][4];
#pragma unroll
            for (int mi = 0; mi < 4; mi++) {
                const __half* p = &sA[buf][wm * 64 + mi * 16 + (lane & 15)][kk + ((lane >> 4) << 3)];
                ldsm4(af[mi][0], af[mi][1], af[mi][2], af[mi][3], smem_u32(p));
            }
#pragma unroll
            for (int mi = 0; mi < 4; mi++)
#pragma unroll
                for (int ni = 0; ni < 4; ni++) {
                    int bi = ni >> 1, s = (ni & 1) << 1;
                    mma16816(acc[mi][ni], af[mi][0], af[mi][1], af[mi][2], af[mi][3],
                             bf[bi][s], bf[bi][s + 1]);
                }
        }
        buf  = (buf  == STAGES - 1) ? 0 : buf + 1;
        wbuf = (wbuf == STAGES - 1) ? 0 : wbuf + 1;
    }

    // ---- epilogue ----
    if (SPEC) {
        // fused OUT=1 head: out[perm[r]] += sum_col relu(acc + b1[col]) * w2[col]
        const float* w2e = w2v + (size_t)eIdx * N;
        const float b2add = (blockIdx.y == 0 && wn == 0) ? __ldg(&b2v[eIdx]) : 0.f;
        float bb0[4], bb1[4], ww0[4], ww1[4];
#pragma unroll
        for (int ni = 0; ni < 4; ni++) {
            int col = n0 + wn * 32 + ni * 8 + ((lane & 3) << 1);
            bb0[ni] = __ldg(&bias[col]); bb1[ni] = __ldg(&bias[col + 1]);
            ww0[ni] = __ldg(&w2e[col]);  ww1[ni] = __ldg(&w2e[col + 1]);
        }
#pragma unroll
        for (int mi = 0; mi < 4; mi++) {
            int r = m0 + wm * 64 + mi * 16 + (lane >> 2);
            float s0 = 0.f, s1 = 0.f;
#pragma unroll
            for (int ni = 0; ni < 4; ni++) {
                s0 = fmaf(fmaxf(acc[mi][ni][0] + bb0[ni], 0.f), ww0[ni], s0);
                s0 = fmaf(fmaxf(acc[mi][ni][1] + bb1[ni], 0.f), ww1[ni], s0);
                s1 = fmaf(fmaxf(acc[mi][ni][2] + bb0[ni], 0.f), ww0[ni], s1);
                s1 = fmaf(fmaxf(acc[mi][ni][3] + bb1[ni], 0.f), ww1[ni], s1);
            }
            s0 += __shfl_xor_sync(0xffffffffu, s0, 1);
            s0 += __shfl_xor_sync(0xffffffffu, s0, 2);
            s1 += __shfl_xor_sync(0xffffffffu, s1, 1);
            s1 += __shfl_xor_sync(0xffffffffu, s1, 2);
            if ((lane & 3) == 0) {
                if (r < mCount)     atomicAdd(outp + rowmap[r],     s0 + b2add);
                if (r + 8 < mCount) atomicAdd(outp + rowmap[r + 8], s1 + b2add);
            }
        }
    } else {
        float bb0[4], bb1[4];
#pragma unroll
        for (int ni = 0; ni < 4; ni++) {
            int col = n0 + wn * 32 + ni * 8 + ((lane & 3) << 1);
            bb0[ni] = bias[col]; bb1[ni] = bias[col + 1];
        }
#pragma unroll
        for (int mi = 0; mi < 4; mi++) {
            int r0 = m0 + wm * 64 + mi * 16 + (lane >> 2);
#pragma unroll
            for (int ni = 0; ni < 4; ni++) {
                int col = n0 + wn * 32 + ni * 8 + ((lane & 3) << 1);
                float v00 = acc[mi][ni][0] + bb0[ni], v01 = acc[mi][ni][1] + bb1[ni];
                float v10 = acc[mi][ni][2] + bb0[ni], v11 = acc[mi][ni][3] + bb1[ni];
                if (RELU) {
                    v00 = fmaxf(v00, 0.f); v01 = fmaxf(v01, 0.f);
                    v10 = fmaxf(v10, 0.f); v11 = fmaxf(v11, 0.f);
                }
                *(__half2*)&C[(size_t)r0 * N + col]       = __floats2half2_rn(v00, v01);
                *(__half2*)&C[(size_t)(r0 + 8) * N + col] = __floats2half2_rn(v10, v11);
            }
        }
    }
}

// ---------------- launch ------------------------------------------------------
extern "C" void kernel_launch(void* const* d_in, const int* in_sizes, int n_in,
                              void* d_out, int out_size) {
    const float* x   = (const float*)d_in[0];
    const void*  dd  = d_in[1];
    const float* eW0 = (const float*)d_in[2];
    const float* eb0 = (const float*)d_in[3];
    const float* eW1 = (const float*)d_in[4];
    const float* eb1 = (const float*)d_in[5];
    const float* eW2 = (const float*)d_in[6];
    const float* eb2 = (const float*)d_in[7];
    const float* sW1 = (const float*)d_in[8];
    const float* sb1 = (const float*)d_in[9];
    const float* sW2 = (const float*)d_in[10];
    const float* sb2 = (const float*)d_in[11];
    float* out = (float*)d_out;

    __half *xh, *z1, *z2, *z, *W0h, *W1h, *W2h, *sW1h;
    cudaGetSymbolAddress((void**)&xh,   g_xh);
    cudaGetSymbolAddress((void**)&z1,   g_z1);
    cudaGetSymbolAddress((void**)&z2,   g_z2);
    cudaGetSymbolAddress((void**)&z,    g_z);
    cudaGetSymbolAddress((void**)&W0h,  g_W0);
    cudaGetSymbolAddress((void**)&W1h,  g_W1);
    cudaGetSymbolAddress((void**)&W2h,  g_W2);
    cudaGetSymbolAddress((void**)&sW1h, g_sW1);

    cudaFuncSetAttribute(gemm_kernel<true,  false>, cudaFuncAttributeMaxDynamicSharedMemorySize, SMEM_BYTES);
    cudaFuncSetAttribute(gemm_kernel<false, false>, cudaFuncAttributeMaxDynamicSharedMemorySize, SMEM_BYTES);
    cudaFuncSetAttribute(gemm_kernel<true,  true>,  cudaFuncAttributeMaxDynamicSharedMemorySize, SMEM_BYTES);

    // fused conversions fp32 -> fp16 (one grid-stride launch, 8 elems/thread)
    {
        CvtArgs a;
        a.s[0] = x;   a.d[0] = xh;
        a.s[1] = eW0; a.d[1] = W0h;
        a.s[2] = eW1; a.d[2] = W1h;
        a.s[3] = eW2; a.d[3] = W2h;
        a.s[4] = sW1; a.d[4] = sW1h;
        int n8s[5] = { BATCH * IN_DIM / 8, IN_DIM * H1 / 8, H1 * H2 / 8,
                       H2 * HIDD / 8, NE * HIDD * SPECH / 8 };
        a.beg[0] = 0;
        for (int k = 0; k < 5; k++) a.beg[k + 1] = a.beg[k] + n8s[k];
        int nthreads = a.beg[5];
        int grid = (nthreads + 255) / 256;
        if (grid > 8 * 148) grid = 8 * 148;   // grid-stride; ~8 waves max
        cvt_all<<<grid, 256>>>(a);
    }

    // first GEMM early so the ncu capture window lands on a GEMM
    gemm_kernel<true,  false><<<dim3(BATCH / BM, H1 / BN), 256, SMEM_BYTES>>>(
        xh, W0h, eb0, z1, nullptr, nullptr, nullptr, H1, IN_DIM);

    // routing (needed before the expert layer only); scatter also zeros out
    setup_kernel<<<1, 32>>>();
    detect_kernel<<<(BATCH / 2 + 255) / 256, 256>>>((const int*)dd, BATCH / 2);
    count_kernel<<<BATCH / 256, 256>>>(dd);
    prefix_kernel<<<1, 1>>>();
    scatter_kernel<<<BATCH / 256, 256>>>(dd, out);

    // rest of the encoder
    gemm_kernel<true,  false><<<dim3(BATCH / BM, H2 / BN), 256, SMEM_BYTES>>>(
        z1, W1h, eb1, z2, nullptr, nullptr, nullptr, H2, H1);
    gemm_kernel<false, false><<<dim3(BATCH / BM, HIDD / BN), 256, SMEM_BYTES>>>(
        z2, W2h, eb2, z, nullptr, nullptr, nullptr, HIDD, H2);

    // routed expert layer with fused OUT=1 head — flattened (expert, m-block)
    gemm_kernel<true, true><<<dim3(SPEC_GRID_X, SPECH / BN), 256, SMEM_BYTES>>>(
        z, sW1h, sb1, nullptr, out, sW2, sb2, SPECH, HIDD);
}

// round 16
// speedup vs baseline: 1.0078x; 1.0078x over previous
#include <cuda_runtime.h>
#include <cuda_fp16.h>
#include <cstdint>

// Problem constants
#define BATCH  16384
#define IN_DIM 1024
#define H1     2048
#define H2     2048
#define HIDD   1024
#define SPECH  2048
#define NE     8

// ---------------- scratch (static device globals; no allocation) -------------
__device__ __half g_xh[(size_t)BATCH * IN_DIM];
__device__ __half g_z1[(size_t)BATCH * H1];
__device__ __half g_z2[(size_t)BATCH * H2];
__device__ __half g_z [(size_t)BATCH * HIDD];
__device__ __half g_W0[(size_t)IN_DIM * H1];
__device__ __half g_W1[(size_t)H1 * H2];
__device__ __half g_W2[(size_t)H2 * HIDD];
__device__ __half g_sW1[(size_t)NE * HIDD * SPECH];
__device__ int g_perm[BATCH];
__device__ int g_off[NE + 1];

// ---------------- helpers ----------------------------------------------------
__device__ __forceinline__ uint32_t smem_u32(const void* p) {
    return (uint32_t)__cvta_generic_to_shared(p);
}
__device__ __forceinline__ void ldsm4(uint32_t& r0, uint32_t& r1, uint32_t& r2, uint32_t& r3, uint32_t a) {
    asm volatile("ldmatrix.sync.aligned.m8n8.x4.shared.b16 {%0,%1,%2,%3},[%4];\n"
                 : "=r"(r0), "=r"(r1), "=r"(r2), "=r"(r3) : "r"(a));
}
__device__ __forceinline__ void ldsm4t(uint32_t& r0, uint32_t& r1, uint32_t& r2, uint32_t& r3, uint32_t a) {
    asm volatile("ldmatrix.sync.aligned.m8n8.x4.trans.shared.b16 {%0,%1,%2,%3},[%4];\n"
                 : "=r"(r0), "=r"(r1), "=r"(r2), "=r"(r3) : "r"(a));
}
__device__ __forceinline__ void mma16816(float* c,
                                         uint32_t a0, uint32_t a1, uint32_t a2, uint32_t a3,
                                         uint32_t b0, uint32_t b1) {
    asm volatile(
        "mma.sync.aligned.m16n8k16.row.col.f32.f16.f16.f32 "
        "{%0,%1,%2,%3},{%4,%5,%6,%7},{%8,%9},{%0,%1,%2,%3};\n"
        : "+f"(c[0]), "+f"(c[1]), "+f"(c[2]), "+f"(c[3])
        : "r"(a0), "r"(a1), "r"(a2), "r"(a3), "r"(b0), "r"(b1));
}
__device__ __forceinline__ void cp16(uint32_t dst, const void* src, uint32_t sz) {
    asm volatile("cp.async.cg.shared.global [%0], [%1], 16, %2;\n"
                 :: "r"(dst), "l"(src), "r"(sz));
}
__device__ __forceinline__ void cp_commit() {
    asm volatile("cp.async.commit_group;\n" ::: "memory");
}
__device__ __forceinline__ void cp_wait_1() {
    asm volatile("cp.async.wait_group 1;\n" ::: "memory");
}

// ---------------- fp32 -> fp16 conversion (8 elems/thread, 16B stores) --------
__global__ void cvt_f2h8(const float* __restrict__ s, __half* __restrict__ d, int n8) {
    int i = blockIdx.x * blockDim.x + threadIdx.x;
    if (i < n8) {
        float4 v0 = ((const float4*)s)[2 * i];
        float4 v1 = ((const float4*)s)[2 * i + 1];
        __half2 h0 = __floats2half2_rn(v0.x, v0.y);
        __half2 h1 = __floats2half2_rn(v0.z, v0.w);
        __half2 h2 = __floats2half2_rn(v1.x, v1.y);
        __half2 h3 = __floats2half2_rn(v1.z, v1.w);
        uint4 o;
        o.x = *reinterpret_cast<uint32_t*>(&h0);
        o.y = *reinterpret_cast<uint32_t*>(&h1);
        o.z = *reinterpret_cast<uint32_t*>(&h2);
        o.w = *reinterpret_cast<uint32_t*>(&h3);
        ((uint4*)d)[i] = o;
    }
}

// ---------------- fused routing: detect+count+prefix+scatter+zero (1 block) ---
__global__ __launch_bounds__(1024) void route_kernel(const void* __restrict__ d,
                                                     float* __restrict__ out) {
    __shared__ int sh[NE];
    __shared__ int sbase[NE];
    __shared__ int sflag;
    const int tid = threadIdx.x;
    if (tid < NE) sh[tid] = 0;
    if (tid == 0) sflag = 1;
    __syncthreads();
    const int* w = (const int*)d;
    // int64 detect: with values 0..7 little-endian, all odd 32-bit words are 0
    bool oddnz = false;
    for (int i = tid; i < BATCH / 2; i += 1024)
        if (w[2 * i + 1] != 0) oddnz = true;
    if (oddnz) sflag = 0;        // benign race: all writers store 0
    __syncthreads();
    const int is64 = sflag;
    const long long* w64 = (const long long*)d;
    // count (smem histogram)
    for (int i = tid; i < BATCH; i += 1024) {
        int e = is64 ? (int)w64[i] : w[i];
        atomicAdd(&sh[e], 1);
    }
    __syncthreads();
    if (tid == 0) {
        int s = 0;
        for (int e = 0; e < NE; e++) { g_off[e] = s; sbase[e] = s; s += sh[e]; }
        g_off[NE] = s;
    }
    __syncthreads();
    // scatter + zero output (expert epilogue accumulates with atomicAdd)
    for (int i = tid; i < BATCH; i += 1024) {
        int e = is64 ? (int)w64[i] : w[i];
        int p = atomicAdd(&sbase[e], 1);
        g_perm[p] = i;
        out[i] = 0.f;
    }
}

// ---------------- fp16 tensor-core GEMM (3-stage cp.async, BK=64) -------------
// C[M,N] = act(A[M,K] @ B[K,N] + bias), A row-major (ldA=K), B row-major [K,N].
// SPEC: flattened grid.x encodes (expert, m-block) via g_off walk; A rows
//   gathered via g_perm; epilogue fuses the OUT=1 head:
//   atomicAdd(out[perm[row]], sum_col relu(acc+b1[col])*w2[col])
//   (+ b2[e] exactly once: blockIdx.y==0 && wn==0).
#define BM 128
#define BN 128
#define BK 64
#define LDA 72
#define LDB 136
#define STAGES 3
#define ABUF_B (BM * LDA * 2)   // 18432 bytes per A stage
#define BBUF_B (BK * LDB * 2)   // 17408 bytes per B stage
#define SMEM_BYTES (STAGES * (ABUF_B + BBUF_B))   // 107520
#define SPEC_GRID_X (BATCH / BM + NE)             // 136: worst case sum of ceils

template <bool RELU, bool SPEC>
__global__ __launch_bounds__(256, 2) void gemm_kernel(
    const __half* __restrict__ A, const __half* __restrict__ Bw,
    const float* __restrict__ bias, __half* __restrict__ C,
    float* __restrict__ outp, const float* __restrict__ w2v,
    const float* __restrict__ b2v, int N, int K) {
    extern __shared__ __align__(16) char dynsm[];
    __half (*sA)[BM][LDA] = reinterpret_cast<__half (*)[BM][LDA]>(dynsm);
    __half (*sB)[BK][LDB] = reinterpret_cast<__half (*)[BK][LDB]>(dynsm + STAGES * ABUF_B);

    int m0 = blockIdx.x * BM;
    const int n0 = blockIdx.y * BN;
    int mCount = BATCH;
    int eIdx = 0;
    const int* rowmap = nullptr;
    if (SPEC) {
        // decode flattened (expert, m-block) from blockIdx.x
        int flat = blockIdx.x;
        int e = 0, mb = flat, nb;
#pragma unroll
        for (e = 0; e < NE; e++) {
            int cnt = g_off[e + 1] - g_off[e];
            nb = (cnt + BM - 1) / BM;
            if (mb < nb) break;
            mb -= nb;
        }
        if (e >= NE) return;
        eIdx = e;
        int beg = g_off[eIdx];
        mCount = g_off[eIdx + 1] - beg;
        m0 = mb * BM;
        rowmap = g_perm + beg;
        Bw   += (size_t)eIdx * K * N;
        bias += (size_t)eIdx * N;
    }

    const int tid  = threadIdx.x;
    const int lane = tid & 31;
    const int warp = tid >> 5;
    const int wm = warp >> 2;  // 0..1  (M)
    const int wn = warp & 3;   // 0..3  (N)

    float acc[4][4][4];
#pragma unroll
    for (int i = 0; i < 4; i++)
#pragma unroll
        for (int j = 0; j < 4; j++)
#pragma unroll
            for (int k = 0; k < 4; k++) acc[i][j][k] = 0.f;

    // ---- per-thread load descriptors ----
    const char* aSrc[4]; uint32_t aSz[4];
    const int aRow0 = tid >> 3, aCs = (tid & 7) << 3;  // cs in halves
#pragma unroll
    for (int li = 0; li < 4; li++) {
        int r = aRow0 + li * 32;
        int gr = m0 + r;
        bool ok = true;
        int grow = gr;
        if (SPEC) {
            ok = gr < mCount;
            grow = ok ? rowmap[gr] : 0;
        }
        aSrc[li] = (const char*)(A + (size_t)grow * K + aCs);
        aSz[li]  = ok ? 16u : 0u;
    }
    const uint32_t aOff0 = smem_u32(&sA[0][aRow0][aCs]);   // + li*32*LDA*2
    const int bRow0 = tid >> 4, bCs = (tid & 15) << 3;
    const char* bSrc0 = (const char*)(Bw + (size_t)bRow0 * N + n0 + bCs);
    const uint32_t bOff0 = smem_u32(&sB[0][bRow0][bCs]);   // + li*16*LDB*2
    const size_t bRowStep = (size_t)16 * N * 2;            // 16 rows in bytes
    const size_t bStep = (size_t)BK * N * 2;               // bytes per k-chunk
    const int nk = K >> 6;

    // prologue: prefetch chunks 0,1 into stages 0,1
#pragma unroll
    for (int s = 0; s < STAGES - 1; s++) {
        if (s < nk) {
            uint32_t ab = (uint32_t)s * ABUF_B;
            uint32_t bb = (uint32_t)s * BBUF_B;
            long ka = (long)s * 128;             // 64 halves = 128 bytes per chunk
#pragma unroll
            for (int li = 0; li < 4; li++)
                cp16(aOff0 + ab + li * (32 * LDA * 2), aSrc[li] + ka, aSz[li]);
#pragma unroll
            for (int li = 0; li < 4; li++)
                cp16(bOff0 + bb + li * (16 * LDB * 2),
                     bSrc0 + (size_t)s * bStep + li * bRowStep, 16u);
        }
        cp_commit();
    }

    int buf = 0, wbuf = STAGES - 1;
    for (int i = 0; i < nk; i++) {
        cp_wait_1();          // chunk i complete (<=1 younger group in flight)
        __syncthreads();      // all warps done with stage being overwritten below
        int nxt = i + STAGES - 1;
        if (nxt < nk) {
            uint32_t ab = (uint32_t)wbuf * ABUF_B;
            uint32_t bb = (uint32_t)wbuf * BBUF_B;
            long ka = (long)nxt * 128;
#pragma unroll
            for (int li = 0; li < 4; li++)
                cp16(aOff0 + ab + li * (32 * LDA * 2), aSrc[li] + ka, aSz[li]);
#pragma unroll
            for (int li = 0; li < 4; li++)
                cp16(bOff0 + bb + li * (16 * LDB * 2),
                     bSrc0 + (size_t)nxt * bStep + li * bRowStep, 16u);
        }
        cp_commit();          // unconditional: keeps group-count invariant at tail

#pragma unroll
        for (int kk = 0; kk < BK; kk += 16) {
            uint32_t bf[2][4];
#pragma unroll
            for (int bi = 0; bi < 2; bi++) {
                const __half* p = &sB[buf][kk + (lane & 15)][wn * 32 + bi * 16 + ((lane >> 4) << 3)];
                ldsm4t(bf[bi][0], bf[bi][1], bf[bi][2], bf[bi][3], smem_u32(p));
            }
            uint32_t af[4][4];
#pragma unroll
            for (int mi = 0; mi < 4; mi++) {
                const __half* p = &sA[buf][wm * 64 + mi * 16 + (lane & 15)][kk + ((lane >> 4) << 3)];
                ldsm4(af[mi][0], af[mi][1], af[mi][2], af[mi][3], smem_u32(p));
            }
#pragma unroll
            for (int mi = 0; mi < 4; mi++)
#pragma unroll
                for (int ni = 0; ni < 4; ni++) {
                    int bi = ni >> 1, s = (ni & 1) << 1;
                    mma16816(acc[mi][ni], af[mi][0], af[mi][1], af[mi][2], af[mi][3],
                             bf[bi][s], bf[bi][s + 1]);
                }
        }
        buf  = (buf  == STAGES - 1) ? 0 : buf + 1;
        wbuf = (wbuf == STAGES - 1) ? 0 : wbuf + 1;
    }

    // ---- epilogue ----
    if (SPEC) {
        // fused OUT=1 head: out[perm[r]] += sum_col relu(acc + b1[col]) * w2[col]
        const float* w2e = w2v + (size_t)eIdx * N;
        const float b2add = (blockIdx.y == 0 && wn == 0) ? __ldg(&b2v[eIdx]) : 0.f;
        float bb0[4], bb1[4], ww0[4], ww1[4];
#pragma unroll
        for (int ni = 0; ni < 4; ni++) {
            int col = n0 + wn * 32 + ni * 8 + ((lane & 3) << 1);
            bb0[ni] = __ldg(&bias[col]); bb1[ni] = __ldg(&bias[col + 1]);
            ww0[ni] = __ldg(&w2e[col]);  ww1[ni] = __ldg(&w2e[col + 1]);
        }
#pragma unroll
        for (int mi = 0; mi < 4; mi++) {
            int r = m0 + wm * 64 + mi * 16 + (lane >> 2);
            float s0 = 0.f, s1 = 0.f;
#pragma unroll
            for (int ni = 0; ni < 4; ni++) {
                s0 = fmaf(fmaxf(acc[mi][ni][0] + bb0[ni], 0.f), ww0[ni], s0);
                s0 = fmaf(fmaxf(acc[mi][ni][1] + bb1[ni], 0.f), ww1[ni], s0);
                s1 = fmaf(fmaxf(acc[mi][ni][2] + bb0[ni], 0.f), ww0[ni], s1);
                s1 = fmaf(fmaxf(acc[mi][ni][3] + bb1[ni], 0.f), ww1[ni], s1);
            }
            s0 += __shfl_xor_sync(0xffffffffu, s0, 1);
            s0 += __shfl_xor_sync(0xffffffffu, s0, 2);
            s1 += __shfl_xor_sync(0xffffffffu, s1, 1);
            s1 += __shfl_xor_sync(0xffffffffu, s1, 2);
            if ((lane & 3) == 0) {
                if (r < mCount)     atomicAdd(outp + rowmap[r],     s0 + b2add);
                if (r + 8 < mCount) atomicAdd(outp + rowmap[r + 8], s1 + b2add);
            }
        }
    } else {
        float bb0[4], bb1[4];
#pragma unroll
        for (int ni = 0; ni < 4; ni++) {
            int col = n0 + wn * 32 + ni * 8 + ((lane & 3) << 1);
            bb0[ni] = bias[col]; bb1[ni] = bias[col + 1];
        }
#pragma unroll
        for (int mi = 0; mi < 4; mi++) {
            int r0 = m0 + wm * 64 + mi * 16 + (lane >> 2);
#pragma unroll
            for (int ni = 0; ni < 4; ni++) {
                int col = n0 + wn * 32 + ni * 8 + ((lane & 3) << 1);
                float v00 = acc[mi][ni][0] + bb0[ni], v01 = acc[mi][ni][1] + bb1[ni];
                float v10 = acc[mi][ni][2] + bb0[ni], v11 = acc[mi][ni][3] + bb1[ni];
                if (RELU) {
                    v00 = fmaxf(v00, 0.f); v01 = fmaxf(v01, 0.f);
                    v10 = fmaxf(v10, 0.f); v11 = fmaxf(v11, 0.f);
                }
                *(__half2*)&C[(size_t)r0 * N + col]       = __floats2half2_rn(v00, v01);
                *(__half2*)&C[(size_t)(r0 + 8) * N + col] = __floats2half2_rn(v10, v11);
            }
        }
    }
}

// ---------------- launch ------------------------------------------------------
extern "C" void kernel_launch(void* const* d_in, const int* in_sizes, int n_in,
                              void* d_out, int out_size) {
    const float* x   = (const float*)d_in[0];
    const void*  dd  = d_in[1];
    const float* eW0 = (const float*)d_in[2];
    const float* eb0 = (const float*)d_in[3];
    const float* eW1 = (const float*)d_in[4];
    const float* eb1 = (const float*)d_in[5];
    const float* eW2 = (const float*)d_in[6];
    const float* eb2 = (const float*)d_in[7];
    const float* sW1 = (const float*)d_in[8];
    const float* sb1 = (const float*)d_in[9];
    const float* sW2 = (const float*)d_in[10];
    const float* sb2 = (const float*)d_in[11];
    float* out = (float*)d_out;

    __half *xh, *z1, *z2, *z, *W0h, *W1h, *W2h, *sW1h;
    cudaGetSymbolAddress((void**)&xh,   g_xh);
    cudaGetSymbolAddress((void**)&z1,   g_z1);
    cudaGetSymbolAddress((void**)&z2,   g_z2);
    cudaGetSymbolAddress((void**)&z,    g_z);
    cudaGetSymbolAddress((void**)&W0h,  g_W0);
    cudaGetSymbolAddress((void**)&W1h,  g_W1);
    cudaGetSymbolAddress((void**)&W2h,  g_W2);
    cudaGetSymbolAddress((void**)&sW1h, g_sW1);

    cudaFuncSetAttribute(gemm_kernel<true,  false>, cudaFuncAttributeMaxDynamicSharedMemorySize, SMEM_BYTES);
    cudaFuncSetAttribute(gemm_kernel<false, false>, cudaFuncAttributeMaxDynamicSharedMemorySize, SMEM_BYTES);
    cudaFuncSetAttribute(gemm_kernel<true,  true>,  cudaFuncAttributeMaxDynamicSharedMemorySize, SMEM_BYTES);

    // conversions fp32 -> fp16 (8 elems/thread, 16B stores)
    {
        int n8;
        n8 = BATCH * IN_DIM / 8;        cvt_f2h8<<<(n8 + 255) / 256, 256>>>(x,   xh,   n8);
        n8 = IN_DIM * H1 / 8;           cvt_f2h8<<<(n8 + 255) / 256, 256>>>(eW0, W0h,  n8);
        n8 = H1 * H2 / 8;               cvt_f2h8<<<(n8 + 255) / 256, 256>>>(eW1, W1h,  n8);
        n8 = H2 * HIDD / 8;             cvt_f2h8<<<(n8 + 255) / 256, 256>>>(eW2, W2h,  n8);
        n8 = NE * HIDD * SPECH / 8;     cvt_f2h8<<<(n8 + 255) / 256, 256>>>(sW1, sW1h, n8);
    }

    // first GEMM early so the ncu capture window lands on a GEMM
    gemm_kernel<true,  false><<<dim3(BATCH / BM, H1 / BN), 256, SMEM_BYTES>>>(
        xh, W0h, eb0, z1, nullptr, nullptr, nullptr, H1, IN_DIM);

    // fused routing + output zeroing (single launch; needed before expert layer)
    route_kernel<<<1, 1024>>>(dd, out);

    // rest of the encoder
    gemm_kernel<true,  false><<<dim3(BATCH / BM, H2 / BN), 256, SMEM_BYTES>>>(
        z1, W1h, eb1, z2, nullptr, nullptr, nullptr, H2, H1);
    gemm_kernel<false, false><<<dim3(BATCH / BM, HIDD / BN), 256, SMEM_BYTES>>>(
        z2, W2h, eb2, z, nullptr, nullptr, nullptr, HIDD, H2);

    // routed expert layer with fused OUT=1 head — flattened (expert, m-block)
    gemm_kernel<true, true><<<dim3(SPEC_GRID_X, SPECH / BN), 256, SMEM_BYTES>>>(
        z, sW1h, sb1, nullptr, out, sW2, sb2, SPECH, HIDD);
}

// round 17
// speedup vs baseline: 1.0226x; 1.0148x over previous
#include <cuda_runtime.h>
#include <cuda_fp16.h>
#include <cstdint>

// Problem constants
#define BATCH  16384
#define IN_DIM 1024
#define H1     2048
#define H2     2048
#define HIDD   1024
#define SPECH  2048
#define NE     8

// ---------------- scratch (static device globals; no allocation) -------------
__device__ __half g_xh[(size_t)BATCH * IN_DIM];
__device__ __half g_z1[(size_t)BATCH * H1];
__device__ __half g_z2[(size_t)BATCH * H2];
__device__ __half g_z [(size_t)BATCH * HIDD];
__device__ __half g_W0[(size_t)IN_DIM * H1];
__device__ __half g_W1[(size_t)H1 * H2];
__device__ __half g_W2[(size_t)H2 * HIDD];
__device__ __half g_sW1[(size_t)NE * HIDD * SPECH];
__device__ int g_perm[BATCH];
__device__ int g_off[NE + 1];

// ---------------- helpers ----------------------------------------------------
__device__ __forceinline__ uint32_t smem_u32(const void* p) {
    return (uint32_t)__cvta_generic_to_shared(p);
}
__device__ __forceinline__ void ldsm4(uint32_t& r0, uint32_t& r1, uint32_t& r2, uint32_t& r3, uint32_t a) {
    asm volatile("ldmatrix.sync.aligned.m8n8.x4.shared.b16 {%0,%1,%2,%3},[%4];\n"
                 : "=r"(r0), "=r"(r1), "=r"(r2), "=r"(r3) : "r"(a));
}
__device__ __forceinline__ void ldsm4t(uint32_t& r0, uint32_t& r1, uint32_t& r2, uint32_t& r3, uint32_t a) {
    asm volatile("ldmatrix.sync.aligned.m8n8.x4.trans.shared.b16 {%0,%1,%2,%3},[%4];\n"
                 : "=r"(r0), "=r"(r1), "=r"(r2), "=r"(r3) : "r"(a));
}
__device__ __forceinline__ void mma16816(float* c,
                                         uint32_t a0, uint32_t a1, uint32_t a2, uint32_t a3,
                                         uint32_t b0, uint32_t b1) {
    asm volatile(
        "mma.sync.aligned.m16n8k16.row.col.f32.f16.f16.f32 "
        "{%0,%1,%2,%3},{%4,%5,%6,%7},{%8,%9},{%0,%1,%2,%3};\n"
        : "+f"(c[0]), "+f"(c[1]), "+f"(c[2]), "+f"(c[3])
        : "r"(a0), "r"(a1), "r"(a2), "r"(a3), "r"(b0), "r"(b1));
}
__device__ __forceinline__ void cp16(uint32_t dst, const void* src, uint32_t sz) {
    asm volatile("cp.async.cg.shared.global [%0], [%1], 16, %2;\n"
                 :: "r"(dst), "l"(src), "r"(sz));
}
__device__ __forceinline__ void cp_commit() {
    asm volatile("cp.async.commit_group;\n" ::: "memory");
}
__device__ __forceinline__ void cp_wait_1() {
    asm volatile("cp.async.wait_group 1;\n" ::: "memory");
}

// ---------------- fp32 -> fp16 conversion (8 elems/thread, 16B stores) --------
__global__ void cvt_f2h8(const float* __restrict__ s, __half* __restrict__ d, int n8) {
    int i = blockIdx.x * blockDim.x + threadIdx.x;
    if (i < n8) {
        float4 v0 = ((const float4*)s)[2 * i];
        float4 v1 = ((const float4*)s)[2 * i + 1];
        __half2 h0 = __floats2half2_rn(v0.x, v0.y);
        __half2 h1 = __floats2half2_rn(v0.z, v0.w);
        __half2 h2 = __floats2half2_rn(v1.x, v1.y);
        __half2 h3 = __floats2half2_rn(v1.z, v1.w);
        uint4 o;
        o.x = *reinterpret_cast<uint32_t*>(&h0);
        o.y = *reinterpret_cast<uint32_t*>(&h1);
        o.z = *reinterpret_cast<uint32_t*>(&h2);
        o.w = *reinterpret_cast<uint32_t*>(&h3);
        ((uint4*)d)[i] = o;
    }
}

// ---------------- fused routing: detect+count+prefix+scatter+zero (1 block) ---
__global__ __launch_bounds__(1024) void route_kernel(const void* __restrict__ d,
                                                     float* __restrict__ out) {
    __shared__ int sh[NE];
    __shared__ int sbase[NE];
    __shared__ int sflag;
    const int tid = threadIdx.x;
    if (tid < NE) sh[tid] = 0;
    if (tid == 0) sflag = 1;
    __syncthreads();
    const int* w = (const int*)d;
    // int64 detect: with values 0..7 little-endian, all odd 32-bit words are 0
    bool oddnz = false;
    for (int i = tid; i < BATCH / 2; i += 1024)
        if (w[2 * i + 1] != 0) oddnz = true;
    if (oddnz) sflag = 0;        // benign race: all writers store 0
    __syncthreads();
    const int is64 = sflag;
    const long long* w64 = (const long long*)d;
    // count (smem histogram)
    for (int i = tid; i < BATCH; i += 1024) {
        int e = is64 ? (int)w64[i] : w[i];
        atomicAdd(&sh[e], 1);
    }
    __syncthreads();
    if (tid == 0) {
        int s = 0;
        for (int e = 0; e < NE; e++) { g_off[e] = s; sbase[e] = s; s += sh[e]; }
        g_off[NE] = s;
    }
    __syncthreads();
    // scatter + zero output (expert epilogue accumulates with atomicAdd)
    for (int i = tid; i < BATCH; i += 1024) {
        int e = is64 ? (int)w64[i] : w[i];
        int p = atomicAdd(&sbase[e], 1);
        g_perm[p] = i;
        out[i] = 0.f;
    }
}

// ---------------- fp16 tensor-core GEMM (3-stage cp.async, BK=64) -------------
// C[M,N] = act(A[M,K] @ B[K,N] + bias), A row-major (ldA=K), B row-major [K,N].
// SPEC: flattened grid.x encodes (expert, m-block) via g_off walk; A rows
//   gathered via g_perm; epilogue fuses the OUT=1 head:
//   atomicAdd(out[perm[row]], sum_col relu(acc+b1[col])*w2[col])
//   (+ b2[e] exactly once: blockIdx.y==0 && wn==0).
#define BM 128
#define BN 128
#define BK 64
#define LDA 72
#define LDB 136
#define STAGES 3
#define ABUF_B (BM * LDA * 2)   // 18432 bytes per A stage
#define BBUF_B (BK * LDB * 2)   // 17408 bytes per B stage
#define SMEM_BYTES (STAGES * (ABUF_B + BBUF_B))   // 107520
#define SPEC_GRID_X (BATCH / BM + NE)             // 136: worst case sum of ceils

template <bool RELU, bool SPEC>
__global__ __launch_bounds__(256, 2) void gemm_kernel(
    const __half* __restrict__ A, const __half* __restrict__ Bw,
    const float* __restrict__ bias, __half* __restrict__ C,
    float* __restrict__ outp, const float* __restrict__ w2v,
    const float* __restrict__ b2v, int N, int K) {
    extern __shared__ __align__(16) char dynsm[];
    __half (*sA)[BM][LDA] = reinterpret_cast<__half (*)[BM][LDA]>(dynsm);
    __half (*sB)[BK][LDB] = reinterpret_cast<__half (*)[BK][LDB]>(dynsm + STAGES * ABUF_B);

    int m0 = blockIdx.x * BM;
    const int n0 = blockIdx.y * BN;
    int mCount = BATCH;
    int eIdx = 0;
    const int* rowmap = nullptr;
    if (SPEC) {
        // decode flattened (expert, m-block) from blockIdx.x
        int flat = blockIdx.x;
        int e = 0, mb = flat, nb;
#pragma unroll
        for (e = 0; e < NE; e++) {
            int cnt = g_off[e + 1] - g_off[e];
            nb = (cnt + BM - 1) / BM;
            if (mb < nb) break;
            mb -= nb;
        }
        if (e >= NE) return;
        eIdx = e;
        int beg = g_off[eIdx];
        mCount = g_off[eIdx + 1] - beg;
        m0 = mb * BM;
        rowmap = g_perm + beg;
        Bw   += (size_t)eIdx * K * N;
        bias += (size_t)eIdx * N;
    }

    const int tid  = threadIdx.x;
    const int lane = tid & 31;
    const int warp = tid >> 5;
    const int wm = warp >> 2;  // 0..1  (M)
    const int wn = warp & 3;   // 0..3  (N)

    float acc[4][4][4];
#pragma unroll
    for (int i = 0; i < 4; i++)
#pragma unroll
        for (int j = 0; j < 4; j++)
#pragma unroll
            for (int k = 0; k < 4; k++) acc[i][j][k] = 0.f;

    // ---- per-thread load descriptors ----
    const char* aSrc[4]; uint32_t aSz[4];
    const int aRow0 = tid >> 3, aCs = (tid & 7) << 3;  // cs in halves
#pragma unroll
    for (int li = 0; li < 4; li++) {
        int r = aRow0 + li * 32;
        int gr = m0 + r;
        bool ok = true;
        int grow = gr;
        if (SPEC) {
            ok = gr < mCount;
            grow = ok ? rowmap[gr] : 0;
        }
        aSrc[li] = (const char*)(A + (size_t)grow * K + aCs);
        aSz[li]  = ok ? 16u : 0u;
    }
    const uint32_t aOff0 = smem_u32(&sA[0][aRow0][aCs]);   // + li*32*LDA*2
    const int bRow0 = tid >> 4, bCs = (tid & 15) << 3;
    const char* bSrc0 = (const char*)(Bw + (size_t)bRow0 * N + n0 + bCs);
    const uint32_t bOff0 = smem_u32(&sB[0][bRow0][bCs]);   // + li*16*LDB*2
    const size_t bRowStep = (size_t)16 * N * 2;            // 16 rows in bytes
    const size_t bStep = (size_t)BK * N * 2;               // bytes per k-chunk
    const int nk = K >> 6;

    // prologue: prefetch chunks 0,1 into stages 0,1
#pragma unroll
    for (int s = 0; s < STAGES - 1; s++) {
        if (s < nk) {
            uint32_t ab = (uint32_t)s * ABUF_B;
            uint32_t bb = (uint32_t)s * BBUF_B;
            long ka = (long)s * 128;             // 64 halves = 128 bytes per chunk
#pragma unroll
            for (int li = 0; li < 4; li++)
                cp16(aOff0 + ab + li * (32 * LDA * 2), aSrc[li] + ka, aSz[li]);
#pragma unroll
            for (int li = 0; li < 4; li++)
                cp16(bOff0 + bb + li * (16 * LDB * 2),
                     bSrc0 + (size_t)s * bStep + li * bRowStep, 16u);
        }
        cp_commit();
    }

    int buf = 0, wbuf = STAGES - 1;
    for (int i = 0; i < nk; i++) {
        cp_wait_1();          // chunk i complete (<=1 younger group in flight)
        __syncthreads();      // all warps done with stage being overwritten below
        int nxt = i + STAGES - 1;
        if (nxt < nk) {
            uint32_t ab = (uint32_t)wbuf * ABUF_B;
            uint32_t bb = (uint32_t)wbuf * BBUF_B;
            long ka = (long)nxt * 128;
#pragma unroll
            for (int li = 0; li < 4; li++)
                cp16(aOff0 + ab + li * (32 * LDA * 2), aSrc[li] + ka, aSz[li]);
#pragma unroll
            for (int li = 0; li < 4; li++)
                cp16(bOff0 + bb + li * (16 * LDB * 2),
                     bSrc0 + (size_t)nxt * bStep + li * bRowStep, 16u);
        }
        cp_commit();          // unconditional: keeps group-count invariant at tail

#pragma unroll
        for (int kk = 0; kk < BK; kk += 16) {
            uint32_t bf[2][4];
#pragma unroll
            for (int bi = 0; bi < 2; bi++) {
                const __half* p = &sB[buf][kk + (lane & 15)][wn * 32 + bi * 16 + ((lane >> 4) << 3)];
                ldsm4t(bf[bi][0], bf[bi][1], bf[bi][2], bf[bi][3], smem_u32(p));
            }
            uint32_t af[4][4];
#pragma unroll
            for (int mi = 0; mi < 4; mi++) {
                const __half* p = &sA[buf][wm * 64 + mi * 16 + (lane & 15)][kk + ((lane >> 4) << 3)];
                ldsm4(af[mi][0], af[mi][1], af[mi][2], af[mi][3], smem_u32(p));
            }
#pragma unroll
            for (int mi = 0; mi < 4; mi++)
#pragma unroll
                for (int ni = 0; ni < 4; ni++) {
                    int bi = ni >> 1, s = (ni & 1) << 1;
                    mma16816(acc[mi][ni], af[mi][0], af[mi][1], af[mi][2], af[mi][3],
                             bf[bi][s], bf[bi][s + 1]);
                }
        }
        buf  = (buf  == STAGES - 1) ? 0 : buf + 1;
        wbuf = (wbuf == STAGES - 1) ? 0 : wbuf + 1;
    }

    // ---- epilogue ----
    if (SPEC) {
        // fused OUT=1 head: out[perm[r]] += sum_col relu(acc + b1[col]) * w2[col]
        const float* w2e = w2v + (size_t)eIdx * N;
        const float b2add = (blockIdx.y == 0 && wn == 0) ? __ldg(&b2v[eIdx]) : 0.f;
        float bb0[4], bb1[4], ww0[4], ww1[4];
#pragma unroll
        for (int ni = 0; ni < 4; ni++) {
            int col = n0 + wn * 32 + ni * 8 + ((lane & 3) << 1);
            bb0[ni] = __ldg(&bias[col]); bb1[ni] = __ldg(&bias[col + 1]);
            ww0[ni] = __ldg(&w2e[col]);  ww1[ni] = __ldg(&w2e[col + 1]);
        }
#pragma unroll
        for (int mi = 0; mi < 4; mi++) {
            int r = m0 + wm * 64 + mi * 16 + (lane >> 2);
            float s0 = 0.f, s1 = 0.f;
#pragma unroll
            for (int ni = 0; ni < 4; ni++) {
                s0 = fmaf(fmaxf(acc[mi][ni][0] + bb0[ni], 0.f), ww0[ni], s0);
                s0 = fmaf(fmaxf(acc[mi][ni][1] + bb1[ni], 0.f), ww1[ni], s0);
                s1 = fmaf(fmaxf(acc[mi][ni][2] + bb0[ni], 0.f), ww0[ni], s1);
                s1 = fmaf(fmaxf(acc[mi][ni][3] + bb1[ni], 0.f), ww1[ni], s1);
            }
            s0 += __shfl_xor_sync(0xffffffffu, s0, 1);
            s0 += __shfl_xor_sync(0xffffffffu, s0, 2);
            s1 += __shfl_xor_sync(0xffffffffu, s1, 1);
            s1 += __shfl_xor_sync(0xffffffffu, s1, 2);
            if ((lane & 3) == 0) {
                if (r < mCount)     atomicAdd(outp + rowmap[r],     s0 + b2add);
                if (r + 8 < mCount) atomicAdd(outp + rowmap[r + 8], s1 + b2add);
            }
        }
    } else {
        float bb0[4], bb1[4];
#pragma unroll
        for (int ni = 0; ni < 4; ni++) {
            int col = n0 + wn * 32 + ni * 8 + ((lane & 3) << 1);
            bb0[ni] = bias[col]; bb1[ni] = bias[col + 1];
        }
#pragma unroll
        for (int mi = 0; mi < 4; mi++) {
            int r0 = m0 + wm * 64 + mi * 16 + (lane >> 2);
#pragma unroll
            for (int ni = 0; ni < 4; ni++) {
                int col = n0 + wn * 32 + ni * 8 + ((lane & 3) << 1);
                float v00 = acc[mi][ni][0] + bb0[ni], v01 = acc[mi][ni][1] + bb1[ni];
                float v10 = acc[mi][ni][2] + bb0[ni], v11 = acc[mi][ni][3] + bb1[ni];
                if (RELU) {
                    v00 = fmaxf(v00, 0.f); v01 = fmaxf(v01, 0.f);
                    v10 = fmaxf(v10, 0.f); v11 = fmaxf(v11, 0.f);
                }
                *(__half2*)&C[(size_t)r0 * N + col]       = __floats2half2_rn(v00, v01);
                *(__half2*)&C[(size_t)(r0 + 8) * N + col] = __floats2half2_rn(v10, v11);
            }
        }
    }
}

// ---------------- launch ------------------------------------------------------
extern "C" void kernel_launch(void* const* d_in, const int* in_sizes, int n_in,
                              void* d_out, int out_size) {
    const float* x   = (const float*)d_in[0];
    const void*  dd  = d_in[1];
    const float* eW0 = (const float*)d_in[2];
    const float* eb0 = (const float*)d_in[3];
    const float* eW1 = (const float*)d_in[4];
    const float* eb1 = (const float*)d_in[5];
    const float* eW2 = (const float*)d_in[6];
    const float* eb2 = (const float*)d_in[7];
    const float* sW1 = (const float*)d_in[8];
    const float* sb1 = (const float*)d_in[9];
    const float* sW2 = (const float*)d_in[10];
    const float* sb2 = (const float*)d_in[11];
    float* out = (float*)d_out;

    __half *xh, *z1, *z2, *z, *W0h, *W1h, *W2h, *sW1h;
    cudaGetSymbolAddress((void**)&xh,   g_xh);
    cudaGetSymbolAddress((void**)&z1,   g_z1);
    cudaGetSymbolAddress((void**)&z2,   g_z2);
    cudaGetSymbolAddress((void**)&z,    g_z);
    cudaGetSymbolAddress((void**)&W0h,  g_W0);
    cudaGetSymbolAddress((void**)&W1h,  g_W1);
    cudaGetSymbolAddress((void**)&W2h,  g_W2);
    cudaGetSymbolAddress((void**)&sW1h, g_sW1);

    cudaFuncSetAttribute(gemm_kernel<true,  false>, cudaFuncAttributeMaxDynamicSharedMemorySize, SMEM_BYTES);
    cudaFuncSetAttribute(gemm_kernel<false, false>, cudaFuncAttributeMaxDynamicSharedMemorySize, SMEM_BYTES);
    cudaFuncSetAttribute(gemm_kernel<true,  true>,  cudaFuncAttributeMaxDynamicSharedMemorySize, SMEM_BYTES);

    // one-time side-stream + events (created on the first, non-captured,
    // correctness call; reused identically in every captured replay)
    static cudaStream_t s2 = nullptr;
    static cudaEvent_t evFork = nullptr, evJoin = nullptr;
    if (s2 == nullptr) {
        cudaStreamCreateWithFlags(&s2, cudaStreamNonBlocking);
        cudaEventCreateWithFlags(&evFork, cudaEventDisableTiming);
        cudaEventCreateWithFlags(&evJoin, cudaEventDisableTiming);
    }

    // main stream: cvt x + W0 (GEMM1 dependencies)
    {
        int n8;
        n8 = BATCH * IN_DIM / 8;  cvt_f2h8<<<(n8 + 255) / 256, 256>>>(x,   xh,  n8);
        n8 = IN_DIM * H1 / 8;     cvt_f2h8<<<(n8 + 255) / 256, 256>>>(eW0, W0h, n8);
    }

    // fork side stream: later-layer weight conversions + routing overlap GEMM1
    cudaEventRecord(evFork, 0);
    cudaStreamWaitEvent(s2, evFork, 0);
    {
        int n8;
        n8 = H1 * H2 / 8;           cvt_f2h8<<<(n8 + 255) / 256, 256, 0, s2>>>(eW1, W1h,  n8);
        n8 = H2 * HIDD / 8;         cvt_f2h8<<<(n8 + 255) / 256, 256, 0, s2>>>(eW2, W2h,  n8);
        n8 = NE * HIDD * SPECH / 8; cvt_f2h8<<<(n8 + 255) / 256, 256, 0, s2>>>(sW1, sW1h, n8);
        route_kernel<<<1, 1024, 0, s2>>>(dd, out);
    }
    cudaEventRecord(evJoin, s2);

    // GEMM1 on main stream (needs only xh, W0h) — runs concurrent with s2
    gemm_kernel<true,  false><<<dim3(BATCH / BM, H1 / BN), 256, SMEM_BYTES>>>(
        xh, W0h, eb0, z1, nullptr, nullptr, nullptr, H1, IN_DIM);

    // join: everything after needs side-stream results
    cudaStreamWaitEvent(0, evJoin, 0);

    gemm_kernel<true,  false><<<dim3(BATCH / BM, H2 / BN), 256, SMEM_BYTES>>>(
        z1, W1h, eb1, z2, nullptr, nullptr, nullptr, H2, H1);
    gemm_kernel<false, false><<<dim3(BATCH / BM, HIDD / BN), 256, SMEM_BYTES>>>(
        z2, W2h, eb2, z, nullptr, nullptr, nullptr, HIDD, H2);

    // routed expert layer with fused OUT=1 head — flattened (expert, m-block)
    gemm_kernel<true, true><<<dim3(SPEC_GRID_X, SPECH / BN), 256, SMEM_BYTES>>>(
        z, sW1h, sb1, nullptr, out, sW2, sb2, SPECH, HIDD);
}